// round 6
// baseline (speedup 1.0000x reference)
#include <cuda_runtime.h>

#define Nn 10000
#define Ee 640000
#define Hh 128
#define Bb 64

// ---------------- scratch (device globals) ----------------------------------
__device__ int   g_cnt[Nn];
__device__ int   g_off[Nn + 1];
__device__ int   g_cur[Nn];
__device__ int   g_csrc[Ee];     // CSR-ordered source ROW OFFSET (src*Hh)
__device__ float g_cnorm[Ee];    // CSR-ordered edge norm
__device__ float g_dinv[Nn];
__device__ float g_tmp[Nn * Hh]; // h @ W (per layer)
__device__ float g_h[Nn * Hh];   // layer output
__device__ float g_pool[Bb * Hh + Bb];

// ---------------- preprocessing ---------------------------------------------
__global__ void pre_zero_kernel() {
    int i = blockIdx.x * blockDim.x + threadIdx.x;
    if (i < Nn) g_cnt[i] = 0;
    if (i < Bb * Hh + Bb) g_pool[i] = 0.0f;
}

__global__ void cnt_kernel(const int* __restrict__ dst) {
    int e = blockIdx.x * blockDim.x + threadIdx.x;
    if (e < Ee) atomicAdd(&g_cnt[dst[e]], 1);
}

// single-block exclusive scan of g_cnt -> g_off; also emits dinv & cur
__global__ void scan_kernel() {
    __shared__ int wsum[32];
    __shared__ int carry_s;
    int t = threadIdx.x, lane = t & 31, w = t >> 5;
    if (t == 0) carry_s = 0;
    __syncthreads();
    for (int base = 0; base < Nn; base += 1024) {
        int i = base + t;
        int v = (i < Nn) ? g_cnt[i] : 0;
        int incl = v;
#pragma unroll
        for (int o = 1; o < 32; o <<= 1) {
            int x = __shfl_up_sync(0xffffffffu, incl, o);
            if (lane >= o) incl += x;
        }
        if (lane == 31) wsum[w] = incl;
        __syncthreads();
        if (w == 0) {
            int x = wsum[lane];
            int s2 = x;
#pragma unroll
            for (int o = 1; o < 32; o <<= 1) {
                int y = __shfl_up_sync(0xffffffffu, s2, o);
                if (lane >= o) s2 += y;
            }
            wsum[lane] = s2 - x;   // exclusive warp offsets
        }
        __syncthreads();
        int carry = carry_s;
        if (i < Nn) {
            int off = carry + wsum[w] + incl - v;
            g_off[i] = off;
            g_cur[i] = off;
            g_dinv[i] = rsqrtf((float)v + 1.0f);  // +1 self loop
        }
        __syncthreads();
        if (t == 1023) carry_s = carry + wsum[31] + incl;
        __syncthreads();
    }
    if (threadIdx.x == 0) g_off[Nn] = carry_s;
}

__global__ void fill_kernel(const int* __restrict__ src, const int* __restrict__ dst) {
    int e = blockIdx.x * blockDim.x + threadIdx.x;
    if (e >= Ee) return;
    int s = src[e];
    int d = dst[e];
    int pos = atomicAdd(&g_cur[d], 1);
    g_csrc[pos] = s * Hh;                       // pre-scaled row offset
    g_cnorm[pos] = g_dinv[s] * g_dinv[d];
}

// ---------------- GEMM: g_tmp = A[Nn,128] @ W[128,128] ----------------------
// 256 threads, tile 64 rows x 128 cols, BK=32.
// thread tile 4 rows x 8 cols: per k -> 4 scalar (broadcast) + 2 LDS.128 + 32 FFMA
__global__ void gemm_kernel(const float* __restrict__ A, const float* __restrict__ W) {
    __shared__ float As[64][36];   // row-major, padded stride (144B, 16B-aligned)
    __shared__ float Ws[32][128];

    int tid = threadIdx.x;
    int tx = tid & 15;     // cols tx*8
    int ty = tid >> 4;     // rows ty*4
    int rowBase = blockIdx.x * 64;

    float acc[4][8];
#pragma unroll
    for (int r = 0; r < 4; r++)
#pragma unroll
        for (int c = 0; c < 8; c++) acc[r][c] = 0.0f;

    for (int kk = 0; kk < Hh; kk += 32) {
        // A tile: 64 rows x 32 k  (512 float4; lanes sweep k4 fastest -> coalesced)
#pragma unroll
        for (int i = 0; i < 2; i++) {
            int lin = i * 256 + tid;
            int row = lin >> 3;        // 0..63
            int k4  = lin & 7;         // 0..7
            int g = rowBase + row;
            float4 v = make_float4(0.f, 0.f, 0.f, 0.f);
            if (g < Nn) v = *(const float4*)&A[g * Hh + kk + k4 * 4];
            *(float4*)&As[row][k4 * 4] = v;
        }
        // W tile: 32 k x 128 cols
#pragma unroll
        for (int i = 0; i < 4; i++) {
            int lin = i * 256 + tid;
            int r = lin >> 5, c4 = lin & 31;
            *(float4*)&Ws[r][c4 * 4] = *(const float4*)&W[(kk + r) * Hh + c4 * 4];
        }
        __syncthreads();
#pragma unroll
        for (int k = 0; k < 32; k++) {
            float4 b0 = *(float4*)&Ws[k][tx * 8];
            float4 b1 = *(float4*)&Ws[k][tx * 8 + 4];
#pragma unroll
            for (int r = 0; r < 4; r++) {
                float a = As[ty * 4 + r][k];
                acc[r][0] += a * b0.x;
                acc[r][1] += a * b0.y;
                acc[r][2] += a * b0.z;
                acc[r][3] += a * b0.w;
                acc[r][4] += a * b1.x;
                acc[r][5] += a * b1.y;
                acc[r][6] += a * b1.z;
                acc[r][7] += a * b1.w;
            }
        }
        __syncthreads();
    }
#pragma unroll
    for (int r = 0; r < 4; r++) {
        int row = rowBase + ty * 4 + r;
        if (row < Nn) {
            *(float4*)&g_tmp[row * Hh + tx * 8] =
                make_float4(acc[r][0], acc[r][1], acc[r][2], acc[r][3]);
            *(float4*)&g_tmp[row * Hh + tx * 8 + 4] =
                make_float4(acc[r][4], acc[r][5], acc[r][6], acc[r][7]);
        }
    }
}

// ---------------- fused gather + epilogue -----------------------------------
// one warp per destination node; register float4 accumulator; no atomics.
// mode: 1 = relu -> g_h, 0 = linear -> g_h, 2 = linear -> pool atomics
__global__ void gather_kernel(const float* __restrict__ bias, int mode,
                              const int* __restrict__ batch) {
    int t = blockIdx.x * blockDim.x + threadIdx.x;
    int i = t >> 5;          // node
    int lane = t & 31;
    if (i >= Nn) return;

    int beg = g_off[i];
    int end = g_off[i + 1];
    int lo4 = lane * 4;

    float4 acc = make_float4(0.f, 0.f, 0.f, 0.f);
    int p = beg;
    for (; p + 3 < end; p += 4) {
        int s0 = g_csrc[p + 0], s1 = g_csrc[p + 1], s2 = g_csrc[p + 2], s3 = g_csrc[p + 3];
        float n0 = g_cnorm[p + 0], n1 = g_cnorm[p + 1], n2 = g_cnorm[p + 2], n3 = g_cnorm[p + 3];
        float4 v0 = *(const float4*)&g_tmp[s0 + lo4];
        float4 v1 = *(const float4*)&g_tmp[s1 + lo4];
        float4 v2 = *(const float4*)&g_tmp[s2 + lo4];
        float4 v3 = *(const float4*)&g_tmp[s3 + lo4];
        acc.x += n0 * v0.x + n1 * v1.x + n2 * v2.x + n3 * v3.x;
        acc.y += n0 * v0.y + n1 * v1.y + n2 * v2.y + n3 * v3.y;
        acc.z += n0 * v0.z + n1 * v1.z + n2 * v2.z + n3 * v3.z;
        acc.w += n0 * v0.w + n1 * v1.w + n2 * v2.w + n3 * v3.w;
    }
    for (; p < end; p++) {
        int s = g_csrc[p];
        float nm = g_cnorm[p];
        float4 v = *(const float4*)&g_tmp[s + lo4];
        acc.x += nm * v.x;
        acc.y += nm * v.y;
        acc.z += nm * v.z;
        acc.w += nm * v.w;
    }

    // self-loop + bias
    float di = g_dinv[i];
    float d2 = di * di;
    float4 tv = ((const float4*)g_tmp)[i * 32 + lane];
    float4 b = ((const float4*)bias)[lane];
    float4 r;
    r.x = acc.x + d2 * tv.x + b.x;
    r.y = acc.y + d2 * tv.y + b.y;
    r.z = acc.z + d2 * tv.z + b.z;
    r.w = acc.w + d2 * tv.w + b.w;

    if (mode == 1) {
        r.x = fmaxf(r.x, 0.f);
        r.y = fmaxf(r.y, 0.f);
        r.z = fmaxf(r.z, 0.f);
        r.w = fmaxf(r.w, 0.f);
        ((float4*)g_h)[i * 32 + lane] = r;
    } else if (mode == 0) {
        ((float4*)g_h)[i * 32 + lane] = r;
    } else {
        int bg = batch[i];
        float* pp = &g_pool[bg * Hh + lo4];
        atomicAdd(pp + 0, r.x);
        atomicAdd(pp + 1, r.y);
        atomicAdd(pp + 2, r.z);
        atomicAdd(pp + 3, r.w);
        if (lane == 0) atomicAdd(&g_pool[Bb * Hh + bg], 1.0f);
    }
}

// ---------------- head -------------------------------------------------------
__global__ void head_kernel(const float* __restrict__ Wp, const float* __restrict__ bp,
                            float* __restrict__ out) {
    int t = blockIdx.x * blockDim.x + threadIdx.x;
    int g = t >> 5;
    int lane = t & 31;
    if (g >= Bb) return;
    float c = g_pool[Bb * Hh + g];
    float inv = 1.0f / fmaxf(c, 1.0f);
    float4 v = ((const float4*)g_pool)[g * 32 + lane];
    float4 w = ((const float4*)Wp)[lane];
    float s = v.x * w.x + v.y * w.y + v.z * w.z + v.w * w.w;
#pragma unroll
    for (int o = 16; o; o >>= 1) s += __shfl_xor_sync(0xffffffffu, s, o);
    if (lane == 0) out[g] = s * inv + bp[0];
}

// ---------------- launch ----------------------------------------------------
extern "C" void kernel_launch(void* const* d_in, const int* in_sizes, int n_in,
                              void* d_out, int out_size) {
    const float* x     = (const float*)d_in[0];
    const int*   ei    = (const int*)d_in[1];
    const int*   batch = (const int*)d_in[2];
    const float* W1    = (const float*)d_in[3];
    const float* b1    = (const float*)d_in[4];
    const float* W2    = (const float*)d_in[5];
    const float* b2    = (const float*)d_in[6];
    const float* W3    = (const float*)d_in[7];
    const float* b3    = (const float*)d_in[8];
    const float* Wp    = (const float*)d_in[9];
    const float* bp    = (const float*)d_in[10];
    float* out = (float*)d_out;

    const int* src = ei;        // edge_index[0]
    const int* dst = ei + Ee;   // edge_index[1]

    float* hbuf = nullptr;
    cudaGetSymbolAddress((void**)&hbuf, g_h);

    const int T = 256;
    int nb_N    = (Nn + T - 1) / T;             // 40
    int nb_E    = (Ee + T - 1) / T;             // 2500
    int nb_Nw   = (Nn * 32 + T - 1) / T;        // 1250
    int nb_gemm = (Nn + 63) / 64;               // 157

    // ---- CSR build + normalization (once, shared by all 3 layers) ----
    pre_zero_kernel<<<nb_N, T>>>();
    cnt_kernel<<<nb_E, T>>>(dst);
    scan_kernel<<<1, 1024>>>();
    fill_kernel<<<nb_E, T>>>(src, dst);

    // ---- layer 1 ----
    gemm_kernel<<<nb_gemm, T>>>(x, W1);
    gather_kernel<<<nb_Nw, T>>>(b1, 1, batch);

    // ---- layer 2 ----
    gemm_kernel<<<nb_gemm, T>>>(hbuf, W2);
    gather_kernel<<<nb_Nw, T>>>(b2, 1, batch);

    // ---- layer 3 (fused with pooling) ----
    gemm_kernel<<<nb_gemm, T>>>(hbuf, W3);
    gather_kernel<<<nb_Nw, T>>>(b3, 2, batch);

    // ---- head ----
    head_kernel<<<(Bb * 32 + T - 1) / T, T>>>(Wp, bp, out);
}

// round 8
// speedup vs baseline: 1.2566x; 1.2566x over previous
#include <cuda_runtime.h>

#define Nn 10000
#define Ee 640000
#define Hh 128
#define Bb 64

#define NB_GEMM ((Nn + 63) / 64)   // 157

// ---------------- scratch (device globals) ----------------------------------
__device__ int   g_cnt[Nn];
__device__ int   g_off[Nn + 1];
__device__ int   g_cur[Nn];
__device__ int2  g_edge[Ee];     // {src*Hh, norm bits} per CSR slot
__device__ float g_dinv[Nn];
__device__ float g_tmp[Nn * Hh]; // h @ W (per layer)
__device__ float g_h[Nn * Hh];   // layer output
__device__ float g_pool[Bb * Hh + Bb];

// ---------------- preprocessing ---------------------------------------------
__global__ void pre_zero_kernel() {
    int i = blockIdx.x * blockDim.x + threadIdx.x;
    if (i < Nn) g_cnt[i] = 0;
    if (i < Bb * Hh + Bb) g_pool[i] = 0.0f;
}

__global__ void cnt_kernel(const int* __restrict__ dst) {
    int e = blockIdx.x * blockDim.x + threadIdx.x;
    if (e < Ee) atomicAdd(&g_cnt[dst[e]], 1);
}

// single-block exclusive scan of g_cnt -> g_off; also emits dinv & cur
__global__ void scan_kernel() {
    __shared__ int wsum[32];
    __shared__ int carry_s;
    int t = threadIdx.x, lane = t & 31, w = t >> 5;
    if (t == 0) carry_s = 0;
    __syncthreads();
    for (int base = 0; base < Nn; base += 1024) {
        int i = base + t;
        int v = (i < Nn) ? g_cnt[i] : 0;
        int incl = v;
#pragma unroll
        for (int o = 1; o < 32; o <<= 1) {
            int x = __shfl_up_sync(0xffffffffu, incl, o);
            if (lane >= o) incl += x;
        }
        if (lane == 31) wsum[w] = incl;
        __syncthreads();
        if (w == 0) {
            int x = wsum[lane];
            int s2 = x;
#pragma unroll
            for (int o = 1; o < 32; o <<= 1) {
                int y = __shfl_up_sync(0xffffffffu, s2, o);
                if (lane >= o) s2 += y;
            }
            wsum[lane] = s2 - x;   // exclusive warp offsets
        }
        __syncthreads();
        int carry = carry_s;
        if (i < Nn) {
            int off = carry + wsum[w] + incl - v;
            g_off[i] = off;
            g_cur[i] = off;
            g_dinv[i] = rsqrtf((float)v + 1.0f);  // +1 self loop
        }
        __syncthreads();
        if (t == 1023) carry_s = carry + wsum[31] + incl;
        __syncthreads();
    }
    if (threadIdx.x == 0) g_off[Nn] = carry_s;
}

// ---------------- GEMM body (round-4 proven version) -------------------------
// 256 threads, tile 64 rows x 128 cols, BK=32; thread tile 8 rows x 4 cols
__device__ __forceinline__ void gemm_body(const float* __restrict__ A,
                                          const float* __restrict__ W,
                                          int rowBase) {
    __shared__ float As[64][32];
    __shared__ float Ws[32][128];

    int tid = threadIdx.x;
    int tx = tid & 31;    // cols tx*4
    int ty = tid >> 5;    // rows ty*8

    float acc[8][4];
#pragma unroll
    for (int r = 0; r < 8; r++)
#pragma unroll
        for (int c = 0; c < 4; c++) acc[r][c] = 0.0f;

    for (int kk = 0; kk < Hh; kk += 32) {
#pragma unroll
        for (int i = 0; i < 2; i++) {
            int lin = tid * 2 + i;          // 0..511 float4 slots (64x8)
            int r = lin >> 3, c4 = lin & 7;
            int row = rowBase + r;
            float4 v = make_float4(0.f, 0.f, 0.f, 0.f);
            if (row < Nn) v = *(const float4*)&A[row * Hh + kk + c4 * 4];
            *(float4*)&As[r][c4 * 4] = v;
        }
#pragma unroll
        for (int i = 0; i < 4; i++) {
            int lin = i * 256 + tid;        // 0..1023 float4 slots (32x32)
            int r = lin >> 5, c4 = lin & 31;
            *(float4*)&Ws[r][c4 * 4] = *(const float4*)&W[(kk + r) * Hh + c4 * 4];
        }
        __syncthreads();
#pragma unroll
        for (int k = 0; k < 32; k++) {
            float4 b = *(float4*)&Ws[k][tx * 4];
#pragma unroll
            for (int r = 0; r < 8; r++) {
                float a = As[ty * 8 + r][k];
                acc[r][0] += a * b.x;
                acc[r][1] += a * b.y;
                acc[r][2] += a * b.z;
                acc[r][3] += a * b.w;
            }
        }
        __syncthreads();
    }
#pragma unroll
    for (int r = 0; r < 8; r++) {
        int row = rowBase + ty * 8 + r;
        if (row < Nn)
            *(float4*)&g_tmp[row * Hh + tx * 4] =
                make_float4(acc[r][0], acc[r][1], acc[r][2], acc[r][3]);
    }
}

__global__ void gemm_kernel(const float* __restrict__ A, const float* __restrict__ W) {
    gemm_body(A, W, blockIdx.x * 64);
}

// ---------------- fused: layer-1 GEMM + CSR fill (independent work) ----------
__global__ void fill_gemm1_kernel(const int* __restrict__ src, const int* __restrict__ dst,
                                  const float* __restrict__ A, const float* __restrict__ W) {
    if (blockIdx.x < NB_GEMM) {
        gemm_body(A, W, blockIdx.x * 64);
    } else {
        int e = (blockIdx.x - NB_GEMM) * blockDim.x + threadIdx.x;
        if (e >= Ee) return;
        int s = src[e];
        int d = dst[e];
        int pos = atomicAdd(&g_cur[d], 1);
        g_edge[pos] = make_int2(s * Hh, __float_as_int(g_dinv[s] * g_dinv[d]));
    }
}

// ---------------- fused gather + epilogue -----------------------------------
// one warp per destination node; register float4 accumulator; no atomics.
// mode: 1 = relu -> g_h, 0 = linear -> g_h, 2 = linear -> pool atomics
__global__ void gather_kernel(const float* __restrict__ bias, int mode,
                              const int* __restrict__ batch) {
    int t = blockIdx.x * blockDim.x + threadIdx.x;
    int i = t >> 5;          // node
    int lane = t & 31;
    if (i >= Nn) return;

    int beg = g_off[i];
    int end = g_off[i + 1];
    int lo4 = lane * 4;

    float4 acc = make_float4(0.f, 0.f, 0.f, 0.f);
    int p = beg;
    for (; p + 3 < end; p += 4) {
        int2 e0 = g_edge[p + 0], e1 = g_edge[p + 1], e2 = g_edge[p + 2], e3 = g_edge[p + 3];
        float n0 = __int_as_float(e0.y), n1 = __int_as_float(e1.y);
        float n2 = __int_as_float(e2.y), n3 = __int_as_float(e3.y);
        float4 v0 = *(const float4*)&g_tmp[e0.x + lo4];
        float4 v1 = *(const float4*)&g_tmp[e1.x + lo4];
        float4 v2 = *(const float4*)&g_tmp[e2.x + lo4];
        float4 v3 = *(const float4*)&g_tmp[e3.x + lo4];
        acc.x += n0 * v0.x + n1 * v1.x + n2 * v2.x + n3 * v3.x;
        acc.y += n0 * v0.y + n1 * v1.y + n2 * v2.y + n3 * v3.y;
        acc.z += n0 * v0.z + n1 * v1.z + n2 * v2.z + n3 * v3.z;
        acc.w += n0 * v0.w + n1 * v1.w + n2 * v2.w + n3 * v3.w;
    }
    for (; p < end; p++) {
        int2 e = g_edge[p];
        float nm = __int_as_float(e.y);
        float4 v = *(const float4*)&g_tmp[e.x + lo4];
        acc.x += nm * v.x;
        acc.y += nm * v.y;
        acc.z += nm * v.z;
        acc.w += nm * v.w;
    }

    // self-loop + bias
    float di = g_dinv[i];
    float d2 = di * di;
    float4 tv = ((const float4*)g_tmp)[i * 32 + lane];
    float4 b = ((const float4*)bias)[lane];
    float4 r;
    r.x = acc.x + d2 * tv.x + b.x;
    r.y = acc.y + d2 * tv.y + b.y;
    r.z = acc.z + d2 * tv.z + b.z;
    r.w = acc.w + d2 * tv.w + b.w;

    if (mode == 1) {
        r.x = fmaxf(r.x, 0.f);
        r.y = fmaxf(r.y, 0.f);
        r.z = fmaxf(r.z, 0.f);
        r.w = fmaxf(r.w, 0.f);
        ((float4*)g_h)[i * 32 + lane] = r;
    } else if (mode == 0) {
        ((float4*)g_h)[i * 32 + lane] = r;
    } else {
        int bg = batch[i];
        float* pp = &g_pool[bg * Hh + lo4];
        atomicAdd(pp + 0, r.x);
        atomicAdd(pp + 1, r.y);
        atomicAdd(pp + 2, r.z);
        atomicAdd(pp + 3, r.w);
        if (lane == 0) atomicAdd(&g_pool[Bb * Hh + bg], 1.0f);
    }
}

// ---------------- head -------------------------------------------------------
__global__ void head_kernel(const float* __restrict__ Wp, const float* __restrict__ bp,
                            float* __restrict__ out) {
    int t = blockIdx.x * blockDim.x + threadIdx.x;
    int g = t >> 5;
    int lane = t & 31;
    if (g >= Bb) return;
    float c = g_pool[Bb * Hh + g];
    float inv = 1.0f / fmaxf(c, 1.0f);
    float4 v = ((const float4*)g_pool)[g * 32 + lane];
    float4 w = ((const float4*)Wp)[lane];
    float s = v.x * w.x + v.y * w.y + v.z * w.z + v.w * w.w;
#pragma unroll
    for (int o = 16; o; o >>= 1) s += __shfl_xor_sync(0xffffffffu, s, o);
    if (lane == 0) out[g] = s * inv + bp[0];
}

// ---------------- launch ----------------------------------------------------
extern "C" void kernel_launch(void* const* d_in, const int* in_sizes, int n_in,
                              void* d_out, int out_size) {
    const float* x     = (const float*)d_in[0];
    const int*   ei    = (const int*)d_in[1];
    const int*   batch = (const int*)d_in[2];
    const float* W1    = (const float*)d_in[3];
    const float* b1    = (const float*)d_in[4];
    const float* W2    = (const float*)d_in[5];
    const float* b2    = (const float*)d_in[6];
    const float* W3    = (const float*)d_in[7];
    const float* b3    = (const float*)d_in[8];
    const float* Wp    = (const float*)d_in[9];
    const float* bp    = (const float*)d_in[10];
    float* out = (float*)d_out;

    const int* src = ei;        // edge_index[0]
    const int* dst = ei + Ee;   // edge_index[1]

    float* hbuf = nullptr;
    cudaGetSymbolAddress((void**)&hbuf, g_h);

    const int T = 256;
    int nb_N  = (Nn + T - 1) / T;             // 40
    int nb_E  = (Ee + T - 1) / T;             // 2500
    int nb_Nw = (Nn * 32 + T - 1) / T;        // 1250

    // ---- CSR build + normalization (once, shared by all 3 layers) ----
    pre_zero_kernel<<<nb_N, T>>>();
    cnt_kernel<<<nb_E, T>>>(dst);
    scan_kernel<<<1, 1024>>>();

    // ---- layer-1 GEMM fused with CSR fill (independent work) ----
    fill_gemm1_kernel<<<NB_GEMM + nb_E, T>>>(src, dst, x, W1);
    gather_kernel<<<nb_Nw, T>>>(b1, 1, batch);

    // ---- layer 2 ----
    gemm_kernel<<<NB_GEMM, T>>>(hbuf, W2);
    gather_kernel<<<nb_Nw, T>>>(b2, 1, batch);

    // ---- layer 3 (fused with pooling) ----
    gemm_kernel<<<NB_GEMM, T>>>(hbuf, W3);
    gather_kernel<<<nb_Nw, T>>>(b3, 2, batch);

    // ---- head ----
    head_kernel<<<(Bb * 32 + T - 1) / T, T>>>(Wp, bp, out);
}

// round 10
// speedup vs baseline: 1.2588x; 1.0018x over previous
#include <cuda_runtime.h>

#define Nn 10000
#define Ee 640000
#define Hh 128
#define Bb 64

#define NB_GEMM   ((Nn + 63) / 64)          // 157
#define NB_GEMM_A 79                        // rows [0, 5056)
#define NB_GEMM_B (NB_GEMM - NB_GEMM_A)     // 78: rows [5056, 10000)
#define EDGE_TPB  256
#define EDGE_BATCH 4
#define NB_EDGE   (Ee / (EDGE_TPB * EDGE_BATCH))   // 625 (exact)

// ---------------- scratch (device globals) ----------------------------------
__device__ int   g_cnt[Nn];          // zeroed by loader (call 1) then by tail
__device__ int   g_off[Nn + 1];
__device__ int   g_cur[Nn];
__device__ int2  g_edge[Ee];         // {src*Hh, norm bits} per CSR slot
__device__ float g_dinv[Nn];
__device__ float g_tmp[Nn * Hh];     // h @ W (per layer)
__device__ float g_h[Nn * Hh];       // layer output
__device__ float g_pool[Bb * Hh + Bb];  // zeroed by loader then by tail

// ---------------- GEMM body (round-4 proven version) -------------------------
// 256 threads, tile 64 rows x 128 cols, BK=32; thread tile 8 rows x 4 cols
__device__ __forceinline__ void gemm_body(const float* __restrict__ A,
                                          const float* __restrict__ W,
                                          int rowBase) {
    __shared__ float As[64][32];
    __shared__ float Ws[32][128];

    int tid = threadIdx.x;
    int tx = tid & 31;    // cols tx*4
    int ty = tid >> 5;    // rows ty*8

    float acc[8][4];
#pragma unroll
    for (int r = 0; r < 8; r++)
#pragma unroll
        for (int c = 0; c < 4; c++) acc[r][c] = 0.0f;

    for (int kk = 0; kk < Hh; kk += 32) {
#pragma unroll
        for (int i = 0; i < 2; i++) {
            int lin = tid * 2 + i;          // 0..511 float4 slots (64x8)
            int r = lin >> 3, c4 = lin & 7;
            int row = rowBase + r;
            float4 v = make_float4(0.f, 0.f, 0.f, 0.f);
            if (row < Nn) v = *(const float4*)&A[row * Hh + kk + c4 * 4];
            *(float4*)&As[r][c4 * 4] = v;
        }
#pragma unroll
        for (int i = 0; i < 4; i++) {
            int lin = i * 256 + tid;        // 0..1023 float4 slots (32x32)
            int r = lin >> 5, c4 = lin & 31;
            *(float4*)&Ws[r][c4 * 4] = *(const float4*)&W[(kk + r) * Hh + c4 * 4];
        }
        __syncthreads();
#pragma unroll
        for (int k = 0; k < 32; k++) {
            float4 b = *(float4*)&Ws[k][tx * 4];
#pragma unroll
            for (int r = 0; r < 8; r++) {
                float a = As[ty * 8 + r][k];
                acc[r][0] += a * b.x;
                acc[r][1] += a * b.y;
                acc[r][2] += a * b.z;
                acc[r][3] += a * b.w;
            }
        }
        __syncthreads();
    }
#pragma unroll
    for (int r = 0; r < 8; r++) {
        int row = rowBase + ty * 8 + r;
        if (row < Nn)
            *(float4*)&g_tmp[row * Hh + tx * 4] =
                make_float4(acc[r][0], acc[r][1], acc[r][2], acc[r][3]);
    }
}

__global__ void gemm_kernel(const float* __restrict__ A, const float* __restrict__ W) {
    gemm_body(A, W, blockIdx.x * 64);
}

// ---------------- phase 1: degree count fused with GEMM1 (rows 0..5055) ------
__global__ void cnt_gemm1a_kernel(const int* __restrict__ dst,
                                  const float* __restrict__ A,
                                  const float* __restrict__ W) {
    if (blockIdx.x < NB_GEMM_A) {
        gemm_body(A, W, blockIdx.x * 64);
    } else {
        int e0 = (blockIdx.x - NB_GEMM_A) * EDGE_TPB + threadIdx.x;
        int d[EDGE_BATCH];
#pragma unroll
        for (int j = 0; j < EDGE_BATCH; j++) {
            int e = e0 + j * (NB_EDGE * EDGE_TPB);
            d[j] = (e < Ee) ? dst[e] : -1;
        }
#pragma unroll
        for (int j = 0; j < EDGE_BATCH; j++)
            if (d[j] >= 0) atomicAdd(&g_cnt[d[j]], 1);
    }
}

// ---------------- scan: exclusive prefix of g_cnt; emits dinv & cur ----------
__global__ void scan_kernel() {
    __shared__ int wsum[32];
    __shared__ int carry_s;
    int t = threadIdx.x, lane = t & 31, w = t >> 5;
    if (t == 0) carry_s = 0;
    __syncthreads();
    for (int base = 0; base < Nn; base += 1024) {
        int i = base + t;
        int v = (i < Nn) ? g_cnt[i] : 0;
        int incl = v;
#pragma unroll
        for (int o = 1; o < 32; o <<= 1) {
            int x = __shfl_up_sync(0xffffffffu, incl, o);
            if (lane >= o) incl += x;
        }
        if (lane == 31) wsum[w] = incl;
        __syncthreads();
        if (w == 0) {
            int x = wsum[lane];
            int s2 = x;
#pragma unroll
            for (int o = 1; o < 32; o <<= 1) {
                int y = __shfl_up_sync(0xffffffffu, s2, o);
                if (lane >= o) s2 += y;
            }
            wsum[lane] = s2 - x;   // exclusive warp offsets
        }
        __syncthreads();
        int carry = carry_s;
        if (i < Nn) {
            int off = carry + wsum[w] + incl - v;
            g_off[i] = off;
            g_cur[i] = off;
            g_dinv[i] = rsqrtf((float)v + 1.0f);  // +1 self loop
        }
        __syncthreads();
        if (t == 1023) carry_s = carry + wsum[31] + incl;
        __syncthreads();
    }
    if (threadIdx.x == 0) g_off[Nn] = carry_s;
}

// ---------------- phase 2: CSR fill fused with GEMM1 (rows 5056..9999) -------
__global__ void fill_gemm1b_kernel(const int* __restrict__ src, const int* __restrict__ dst,
                                   const float* __restrict__ A, const float* __restrict__ W) {
    if (blockIdx.x < NB_GEMM_B) {
        gemm_body(A, W, (blockIdx.x + NB_GEMM_A) * 64);
    } else {
        int e0 = (blockIdx.x - NB_GEMM_B) * EDGE_TPB + threadIdx.x;
        int s[EDGE_BATCH], d[EDGE_BATCH];
        float nm[EDGE_BATCH];
#pragma unroll
        for (int j = 0; j < EDGE_BATCH; j++) {
            int e = e0 + j * (NB_EDGE * EDGE_TPB);
            if (e < Ee) {
                s[j] = src[e];
                d[j] = dst[e];
            } else {
                s[j] = -1;
                d[j] = 0;
            }
        }
#pragma unroll
        for (int j = 0; j < EDGE_BATCH; j++)
            if (s[j] >= 0) nm[j] = g_dinv[s[j]] * g_dinv[d[j]];
        int pos[EDGE_BATCH];
#pragma unroll
        for (int j = 0; j < EDGE_BATCH; j++)
            pos[j] = (s[j] >= 0) ? atomicAdd(&g_cur[d[j]], 1) : -1;
#pragma unroll
        for (int j = 0; j < EDGE_BATCH; j++)
            if (pos[j] >= 0)
                g_edge[pos[j]] = make_int2(s[j] * Hh, __float_as_int(nm[j]));
    }
}

// ---------------- fused gather + epilogue -----------------------------------
// one warp per destination node; register float4 accumulator; no atomics.
// mode: 1 = relu -> g_h, 0 = linear -> g_h, 2 = linear -> pool atomics
__global__ void gather_kernel(const float* __restrict__ bias, int mode,
                              const int* __restrict__ batch) {
    int t = blockIdx.x * blockDim.x + threadIdx.x;
    int i = t >> 5;          // node
    int lane = t & 31;
    if (i >= Nn) return;

    int beg = g_off[i];
    int end = g_off[i + 1];
    int lo4 = lane * 4;

    float4 acc = make_float4(0.f, 0.f, 0.f, 0.f);
    int p = beg;
    for (; p + 3 < end; p += 4) {
        int2 e0 = g_edge[p + 0], e1 = g_edge[p + 1], e2 = g_edge[p + 2], e3 = g_edge[p + 3];
        float n0 = __int_as_float(e0.y), n1 = __int_as_float(e1.y);
        float n2 = __int_as_float(e2.y), n3 = __int_as_float(e3.y);
        float4 v0 = *(const float4*)&g_tmp[e0.x + lo4];
        float4 v1 = *(const float4*)&g_tmp[e1.x + lo4];
        float4 v2 = *(const float4*)&g_tmp[e2.x + lo4];
        float4 v3 = *(const float4*)&g_tmp[e3.x + lo4];
        acc.x += n0 * v0.x + n1 * v1.x + n2 * v2.x + n3 * v3.x;
        acc.y += n0 * v0.y + n1 * v1.y + n2 * v2.y + n3 * v3.y;
        acc.z += n0 * v0.z + n1 * v1.z + n2 * v2.z + n3 * v3.z;
        acc.w += n0 * v0.w + n1 * v1.w + n2 * v2.w + n3 * v3.w;
    }
    for (; p < end; p++) {
        int2 e = g_edge[p];
        float nm = __int_as_float(e.y);
        float4 v = *(const float4*)&g_tmp[e.x + lo4];
        acc.x += nm * v.x;
        acc.y += nm * v.y;
        acc.z += nm * v.z;
        acc.w += nm * v.w;
    }

    // self-loop + bias
    float di = g_dinv[i];
    float d2 = di * di;
    float4 tv = ((const float4*)g_tmp)[i * 32 + lane];
    float4 b = ((const float4*)bias)[lane];
    float4 r;
    r.x = acc.x + d2 * tv.x + b.x;
    r.y = acc.y + d2 * tv.y + b.y;
    r.z = acc.z + d2 * tv.z + b.z;
    r.w = acc.w + d2 * tv.w + b.w;

    if (mode == 1) {
        r.x = fmaxf(r.x, 0.f);
        r.y = fmaxf(r.y, 0.f);
        r.z = fmaxf(r.z, 0.f);
        r.w = fmaxf(r.w, 0.f);
        ((float4*)g_h)[i * 32 + lane] = r;
    } else if (mode == 0) {
        ((float4*)g_h)[i * 32 + lane] = r;
    } else {
        int bg = batch[i];
        float* pp = &g_pool[bg * Hh + lo4];
        atomicAdd(pp + 0, r.x);
        atomicAdd(pp + 1, r.y);
        atomicAdd(pp + 2, r.z);
        atomicAdd(pp + 3, r.w);
        if (lane == 0) atomicAdd(&g_pool[Bb * Hh + bg], 1.0f);
    }
}

// ---------------- head + tail-zero for next replay ---------------------------
// blocks 0..7: compute head for 64 graphs, then zero own pool slice.
// blocks 8..47: zero g_cnt for the next graph replay.
__global__ void head_tail_kernel(const float* __restrict__ Wp, const float* __restrict__ bp,
                                 float* __restrict__ out) {
    if (blockIdx.x < 8) {
        int t = blockIdx.x * blockDim.x + threadIdx.x;
        int g = t >> 5;
        int lane = t & 31;
        if (g >= Bb) return;
        float c = g_pool[Bb * Hh + g];
        float inv = 1.0f / fmaxf(c, 1.0f);
        float4 v = ((const float4*)g_pool)[g * 32 + lane];
        float4 w = ((const float4*)Wp)[lane];
        float s = v.x * w.x + v.y * w.y + v.z * w.z + v.w * w.w;
#pragma unroll
        for (int o = 16; o; o >>= 1) s += __shfl_xor_sync(0xffffffffu, s, o);
        if (lane == 0) {
            out[g] = s * inv + bp[0];
            g_pool[Bb * Hh + g] = 0.0f;           // re-zero count for next replay
        }
        ((float4*)g_pool)[g * 32 + lane] = make_float4(0.f, 0.f, 0.f, 0.f);
    } else {
        int i = (blockIdx.x - 8) * blockDim.x + threadIdx.x;
        if (i < Nn) g_cnt[i] = 0;                 // re-zero degrees for next replay
    }
}

// ---------------- launch ----------------------------------------------------
extern "C" void kernel_launch(void* const* d_in, const int* in_sizes, int n_in,
                              void* d_out, int out_size) {
    const float* x     = (const float*)d_in[0];
    const int*   ei    = (const int*)d_in[1];
    const int*   batch = (const int*)d_in[2];
    const float* W1    = (const float*)d_in[3];
    const float* b1    = (const float*)d_in[4];
    const float* W2    = (const float*)d_in[5];
    const float* b2    = (const float*)d_in[6];
    const float* W3    = (const float*)d_in[7];
    const float* b3    = (const float*)d_in[8];
    const float* Wp    = (const float*)d_in[9];
    const float* bp    = (const float*)d_in[10];
    float* out = (float*)d_out;

    const int* src = ei;        // edge_index[0]
    const int* dst = ei + Ee;   // edge_index[1]

    float* hbuf = nullptr;
    cudaGetSymbolAddress((void**)&hbuf, g_h);

    const int T = 256;
    int nb_Nw = (Nn * 32 + T - 1) / T;        // 1250

    // phase 1: degree count || GEMM1 (first half of rows)
    cnt_gemm1a_kernel<<<NB_GEMM_A + NB_EDGE, T>>>(dst, x, W1);
    // offsets + dinv
    scan_kernel<<<1, 1024>>>();
    // phase 2: CSR fill || GEMM1 (second half of rows)
    fill_gemm1b_kernel<<<NB_GEMM_B + NB_EDGE, T>>>(src, dst, x, W1);

    // layer 1 aggregate
    gather_kernel<<<nb_Nw, T>>>(b1, 1, batch);

    // layer 2
    gemm_kernel<<<NB_GEMM, T>>>(hbuf, W2);
    gather_kernel<<<nb_Nw, T>>>(b2, 1, batch);

    // layer 3 (fused with pooling)
    gemm_kernel<<<NB_GEMM, T>>>(hbuf, W3);
    gather_kernel<<<nb_Nw, T>>>(b3, 2, batch);

    // head + tail-zero (pool & cnt reset for next replay)
    head_tail_kernel<<<8 + (Nn + T - 1) / T, T>>>(Wp, bp, out);
}